// round 5
// baseline (speedup 1.0000x reference)
#include <cuda_runtime.h>
#include <cuda_bf16.h>
#include <stdint.h>

#define Nn   8192
#define FIN  512
#define FOUT 128
#define HID  16
#define NF   (Nn*FOUT)

// ---------------- scratch (device globals: allocation-free) ----------------
__device__ float        g_hf[Nn * FOUT];       // h fp32, 4MB
__device__ unsigned     g_amaxu[FOUT];         // per-feature absmax (float bits)
__device__ signed char  g_q1[FOUT * Nn];       // limb1 s8, transposed [feat][node]
__device__ signed char  g_q2[FOUT * Nn];       // limb2 s8
__device__ float        g_part[2 * NF];        // K-split partial sums
__device__ float        g_degp[2 * Nn];        // K-split partial degrees
__device__ float        g_qpart[128];          // per-block qmp partials

// ---------------- PTX helpers ----------------
__device__ __forceinline__ uint32_t smem_u32(const void* p) {
    uint32_t a;
    asm("{ .reg .u64 t; cvta.to.shared.u64 t, %1; cvt.u32.u64 %0, t; }" : "=r"(a) : "l"(p));
    return a;
}
#define CP16(dst, src) \
    asm volatile("cp.async.cg.shared.global [%0], [%1], 16;" :: "r"(dst), "l"(src) : "memory")
#define CP_COMMIT() asm volatile("cp.async.commit_group;" ::: "memory")
#define CP_WAIT1()  asm volatile("cp.async.wait_group 1;" ::: "memory")

#define IMMA16832(acc, a, b0, b1) \
    asm volatile("mma.sync.aligned.m16n8k32.row.col.s32.s8.s8.s32 " \
        "{%0,%1,%2,%3},{%4,%5,%6,%7},{%8,%9},{%0,%1,%2,%3};" \
        : "+r"((acc)[0]), "+r"((acc)[1]), "+r"((acc)[2]), "+r"((acc)[3]) \
        : "r"((a)[0]), "r"((a)[1]), "r"((a)[2]), "r"((a)[3]), "r"(b0), "r"(b1))

__device__ __forceinline__ int dp4a1(uint32_t a, int c) {
    asm("dp4a.s32.s32 %0, %1, %2, %0;" : "+r"(c) : "r"(a), "r"(0x01010101));
    return c;
}
__device__ __forceinline__ uint32_t pack01(int4 v) {
    uint32_t p01 = __byte_perm((uint32_t)v.x, (uint32_t)v.y, 0x0040);
    uint32_t p23 = __byte_perm((uint32_t)v.z, (uint32_t)v.w, 0x0040);
    return __byte_perm(p01, p23, 0x5410);
}

// ---------------- kernel 0: init absmax ----------------
__global__ void k0_init() { if (threadIdx.x < FOUT) g_amaxu[threadIdx.x] = 0u; }

// ---------------- kernel 1: h = x@W (fp32), absmax, qmp partials -----------
// smem: xs[64][36] @0 (9216B); ws[32][132] @9216 (16896B); v1s[16][128] @26112
// (8192B); sml @34304 (256B); h_s[64][133] @34560 (34048B)
#define K1_SMEM 68608

__global__ void __launch_bounds__(512) k1_feat(
    const float* __restrict__ x, const float* __restrict__ W,
    const float* __restrict__ w1, const float* __restrict__ b1,
    const float* __restrict__ w21, const float* __restrict__ b21,
    const float* __restrict__ w22, const float* __restrict__ b22)
{
    extern __shared__ __align__(16) char sm1[];
    float* xs  = (float*)sm1;
    float* ws  = (float*)(sm1 + 9216);
    float* v1s = (float*)(sm1 + 26112);
    float* sml = (float*)(sm1 + 34304);
    float* h_s = (float*)(sm1 + 34560);

    const int t  = threadIdx.x;
    const int m0 = blockIdx.x * 64;

    for (int i = t; i < HID * FOUT; i += 512) {
        int hh = i >> 7, c = i & 127;
        v1s[i] = w1[hh * 256 + c] + w1[hh * 256 + 128 + c];
    }
    if (t < 16) { sml[t] = b1[t]; sml[16 + t] = w21[t]; sml[32 + t] = w22[t]; }
    if (t == 0) { sml[48] = b21[0]; sml[49] = b22[0]; }

    const int r0 = (t >> 4) << 1;      // 2 rows
    const int cb = (t & 15) << 1;
    unsigned long long acc[2][4];
    #pragma unroll
    for (int i = 0; i < 2; i++)
        #pragma unroll
        for (int j = 0; j < 4; j++) acc[i][j] = 0ull;

    for (int kc = 0; kc < 16; kc++) {
        const int k0i = kc * 32;
        {   // xs: 64x32 floats = 512 float4, one per thread
            int rr = t >> 3, g = t & 7;
            *(float4*)&xs[rr * 36 + g * 4] =
                *(const float4*)&x[(size_t)(m0 + rr) * FIN + k0i + g * 4];
        }
        #pragma unroll
        for (int i = 0; i < 2; i++) {   // ws: 32x128 = 1024 float4
            int item = t + 512 * i;
            int kk = item >> 5, cg = (item & 31) << 2;
            *(float4*)&ws[kk * 132 + cg] =
                *(const float4*)&W[(size_t)(k0i + kk) * FOUT + cg];
        }
        __syncthreads();
        #pragma unroll 8
        for (int kk = 0; kk < 32; kk++) {
            unsigned long long aa[2];
            #pragma unroll
            for (int i = 0; i < 2; i++) {
                float a = xs[(r0 + i) * 36 + kk];
                asm("mov.b64 %0, {%1, %1};" : "=l"(aa[i]) : "r"(__float_as_uint(a)));
            }
            #pragma unroll
            for (int j = 0; j < 4; j++) {
                unsigned long long bp = *(const unsigned long long*)&ws[kk * 132 + cb + 32 * j];
                #pragma unroll
                for (int i = 0; i < 2; i++)
                    asm("fma.rn.f32x2 %0, %1, %2, %0;" : "+l"(acc[i][j]) : "l"(aa[i]), "l"(bp));
            }
        }
        __syncthreads();
    }
    #pragma unroll
    for (int i = 0; i < 2; i++)
        #pragma unroll
        for (int j = 0; j < 4; j++) {
            uint32_t lo, hi;
            asm("mov.b64 {%0, %1}, %2;" : "=r"(lo), "=r"(hi) : "l"(acc[i][j]));
            h_s[(r0 + i) * 133 + cb + 32 * j]     = __uint_as_float(lo);
            h_s[(r0 + i) * 133 + cb + 32 * j + 1] = __uint_as_float(hi);
        }
    __syncthreads();

    // h fp32 out (coalesced)
    #pragma unroll
    for (int ii = 0; ii < 4; ii++) {
        int item = t + 512 * ii;                  // 0..2047
        int rr = item >> 5, cg = (item & 31) << 2;
        float4 v = make_float4(h_s[rr * 133 + cg],     h_s[rr * 133 + cg + 1],
                               h_s[rr * 133 + cg + 2], h_s[rr * 133 + cg + 3]);
        *(float4*)&g_hf[(size_t)(m0 + rr) * FOUT + cg] = v;
    }
    // per-feature absmax
    if (t < FOUT) {
        float m = 0.0f;
        for (int r = 0; r < 64; r++) m = fmaxf(m, fabsf(h_s[r * 133 + t]));
        atomicMax(&g_amaxu[t], __float_as_uint(m));
    }

    // qmp partials: 16 warps x 4 rows
    const int w = t >> 5, l = t & 31;
    float contrib = 0.0f;
    for (int rr = w * 4; rr < w * 4 + 4; rr++) {
        float hv0 = h_s[rr * 133 + l];
        float hv1 = h_s[rr * 133 + l + 32];
        float hv2 = h_s[rr * 133 + l + 64];
        float hv3 = h_s[rr * 133 + l + 96];
        float mu = 0.0f, lv = 0.0f;
        #pragma unroll
        for (int hh = 0; hh < 16; hh++) {
            const float* vr = &v1s[hh * 128];
            float s = hv0 * vr[l] + hv1 * vr[l + 32] + hv2 * vr[l + 64] + hv3 * vr[l + 96];
            #pragma unroll
            for (int o = 16; o > 0; o >>= 1) s += __shfl_xor_sync(0xffffffffu, s, o);
            float u = s + sml[hh];
            u = u > 0.0f ? u : 0.0f;
            mu += u * sml[16 + hh];
            lv += u * sml[32 + hh];
        }
        if (l == 0) {
            mu += sml[48]; lv += sml[49];
            float sig = (lv > 20.0f) ? lv : log1pf(expf(lv));
            contrib += 0.5f * mu * mu - logf(sig);
        }
    }
    if (l == 0) xs[w] = contrib;      // xs region is free now
    __syncthreads();
    if (t == 0) {
        float s = 0.0f;
        #pragma unroll
        for (int i = 0; i < 16; i++) s += xs[i];
        g_qpart[blockIdx.x] = s;
    }
}

// ---------------- kernel 1b: transpose + 2-limb s8 quantize ----------------
// smem: hs[64][132] f32 (33792B) + sc[128] (512B)
#define K1B_SMEM 34304

__global__ void __launch_bounds__(512) k1b_quant()
{
    extern __shared__ __align__(16) char smb[];
    float* hs = (float*)smb;
    float* sc = (float*)(smb + 33792);
    const int t = threadIdx.x;
    const int m0 = blockIdx.x * 64;

    if (t < FOUT) {
        float amax = __uint_as_float(g_amaxu[t]);
        sc[t] = amax > 0.0f ? 127.0f / amax : 0.0f;
    }
    #pragma unroll
    for (int i = 0; i < 4; i++) {
        int item = t + 512 * i;
        int rr = item >> 5, cg = (item & 31) << 2;
        *(float4*)&hs[rr * 132 + cg] = *(const float4*)&g_hf[(size_t)(m0 + rr) * FOUT + cg];
    }
    __syncthreads();

    const int n = t >> 2, g = t & 3;      // feature, 16-row group
    const float inv = sc[n];
    uint32_t b1[4] = {0, 0, 0, 0}, b2[4] = {0, 0, 0, 0};
    #pragma unroll
    for (int j = 0; j < 16; j++) {
        float h = hs[(g * 16 + j) * 132 + n];
        float f = h * inv;
        int q1 = __float2int_rn(f);
        int q2 = __float2int_rn((f - (float)q1) * 254.0f);
        b1[j >> 2] |= (uint32_t)(q1 & 0xFF) << ((j & 3) * 8);
        b2[j >> 2] |= (uint32_t)(q2 & 0xFF) << ((j & 3) * 8);
    }
    size_t off = (size_t)n * Nn + m0 + g * 16;
    *(uint4*)(g_q1 + off) = make_uint4(b1[0], b1[1], b1[2], b1[3]);
    *(uint4*)(g_q2 + off) = make_uint4(b2[0], b2[1], b2[2], b2[3]);
}

// ---------------- kernel 2: masked aggregation via s8 IMMA -----------------
// Grid 128: CTA (mt, ksp): rows [mt*128,+128), K-half [ksp*4096,+4096).
// Buffer: A int32 [128][72] (36864B) | B1 s8 [128][80] (10240B) | B2 (10240B)
#define ASTRIDE 288
#define OFFB1   36864
#define OFFB2   47104
#define BUFSZ   57344
#define SCOFF   (2*BUFSZ)
#define K2_SMEM (SCOFF + 512)
#define NCH2    64

__global__ void __launch_bounds__(512, 1) k2_aggr(const int* __restrict__ adj)
{
    extern __shared__ __align__(128) char sm2[];
    const uint32_t sb = smem_u32(sm2);
    const int t = threadIdx.x;
    const int mt = blockIdx.x >> 1, ksp = blockIdx.x & 1;
    const int m0 = mt * 128;
    const int kbase = ksp * 4096;

    const int w = t >> 5, l = t & 31;
    const int wm = w & 3, wn = w >> 2;     // 4x4 warps, warp tile 32x32

    float* sc = (float*)(sm2 + SCOFF);
    if (t < FOUT) {
        float amax = __uint_as_float(g_amaxu[t]);
        sc[t] = amax * (1.0f / 127.0f);
    }

#define LOAD_CHUNK(c, buf) do {                                                 \
    const size_t _ko = (size_t)kbase + (size_t)(c) * 64;                        \
    _Pragma("unroll")                                                           \
    for (int _i = 0; _i < 4; _i++) {                                            \
        int _idx = t + 512 * _i; int _r = _idx >> 4, _c = _idx & 15;            \
        CP16(sb + (buf) * BUFSZ + _r * ASTRIDE + _c * 16,                       \
             (const char*)(adj + (size_t)(m0 + _r) * Nn + _ko + _c * 4));       \
    }                                                                           \
    { int _n = t >> 2, _c = t & 3;                                              \
      CP16(sb + (buf) * BUFSZ + OFFB1 + _n * 80 + _c * 16,                      \
           (const char*)g_q1 + (size_t)_n * Nn + _ko + _c * 16);                \
      CP16(sb + (buf) * BUFSZ + OFFB2 + _n * 80 + _c * 16,                      \
           (const char*)g_q2 + (size_t)_n * Nn + _ko + _c * 16); }              \
} while (0)

    int acc1[2][4][4], acc2[2][4][4];
    #pragma unroll
    for (int m = 0; m < 2; m++)
        #pragma unroll
        for (int p = 0; p < 4; p++)
            #pragma unroll
            for (int q = 0; q < 4; q++) { acc1[m][p][q] = 0; acc2[m][p][q] = 0; }
    int da[2][2] = {{0, 0}, {0, 0}};

    LOAD_CHUNK(0, 0); CP_COMMIT();
    LOAD_CHUNK(1, 1); CP_COMMIT();

    for (int c = 0; c < NCH2; c++) {
        CP_WAIT1();
        __syncthreads();
        const int buf = c & 1;
        const char* smA  = sm2 + buf * BUFSZ;
        const char* smB1 = sm2 + buf * BUFSZ + OFFB1;
        const char* smB2 = sm2 + buf * BUFSZ + OFFB2;

        #pragma unroll
        for (int ks = 0; ks < 2; ks++) {
            const int kk = ks * 32;
            uint32_t a[2][4];
            #pragma unroll
            for (int m = 0; m < 2; m++) {
                const int row = wm * 32 + m * 16 + (l >> 2);
                const char* base = smA + row * ASTRIDE + (kk + 4 * (l & 3)) * 4;
                int4 v0 = *(const int4*)base;
                int4 v1 = *(const int4*)(base + 8 * ASTRIDE);
                int4 v2 = *(const int4*)(base + 64);
                int4 v3 = *(const int4*)(base + 8 * ASTRIDE + 64);
                a[m][0] = pack01(v0); a[m][1] = pack01(v1);
                a[m][2] = pack01(v2); a[m][3] = pack01(v3);
                if (wn == 0) {
                    da[m][0] = dp4a1(a[m][0], dp4a1(a[m][2], da[m][0]));
                    da[m][1] = dp4a1(a[m][1], dp4a1(a[m][3], da[m][1]));
                }
            }
            #pragma unroll
            for (int p = 0; p < 4; p++) {
                const int n = wn * 32 + p * 8 + (l >> 2);
                const int boff = n * 80 + kk + 4 * (l & 3);
                uint32_t b0 = *(const uint32_t*)(smB1 + boff);
                uint32_t b1 = *(const uint32_t*)(smB1 + boff + 16);
                IMMA16832(acc1[0][p], a[0], b0, b1);
                IMMA16832(acc1[1][p], a[1], b0, b1);
                b0 = *(const uint32_t*)(smB2 + boff);
                b1 = *(const uint32_t*)(smB2 + boff + 16);
                IMMA16832(acc2[0][p], a[0], b0, b1);
                IMMA16832(acc2[1][p], a[1], b0, b1);
            }
        }
        __syncthreads();
        if (c + 2 < NCH2) LOAD_CHUNK(c + 2, buf);
        CP_COMMIT();
    }
#undef LOAD_CHUNK

    // epilogue: combine limbs, write K-split partials
    const float INV254 = 1.0f / 254.0f;
    float* slab = g_part + (size_t)ksp * NF;
    #pragma unroll
    for (int m = 0; m < 2; m++) {
        const int row = m0 + wm * 32 + m * 16 + (l >> 2);
        #pragma unroll
        for (int p = 0; p < 4; p++) {
            const int col = wn * 32 + p * 8 + 2 * (l & 3);
            const float s0 = sc[col], s1 = sc[col + 1];
            float v0 = s0 * fmaf((float)acc2[m][p][0], INV254, (float)acc1[m][p][0]);
            float v1 = s1 * fmaf((float)acc2[m][p][1], INV254, (float)acc1[m][p][1]);
            float v2 = s0 * fmaf((float)acc2[m][p][2], INV254, (float)acc1[m][p][2]);
            float v3 = s1 * fmaf((float)acc2[m][p][3], INV254, (float)acc1[m][p][3]);
            *(float2*)&slab[(size_t)row * FOUT + col]       = make_float2(v0, v1);
            *(float2*)&slab[(size_t)(row + 8) * FOUT + col] = make_float2(v2, v3);
        }
    }
    if (wn == 0) {
        #pragma unroll
        for (int m = 0; m < 2; m++) {
            int d0 = da[m][0], d1 = da[m][1];
            d0 += __shfl_xor_sync(0xffffffffu, d0, 1);
            d0 += __shfl_xor_sync(0xffffffffu, d0, 2);
            d1 += __shfl_xor_sync(0xffffffffu, d1, 1);
            d1 += __shfl_xor_sync(0xffffffffu, d1, 2);
            if ((l & 3) == 0) {
                const int row = m0 + wm * 32 + m * 16 + (l >> 2);
                g_degp[ksp * Nn + row]     = (float)d0;
                g_degp[ksp * Nn + row + 8] = (float)d1;
            }
        }
    }
}

// ---------------- kernel 3: combine K-halves, scale, elu, qmp --------------
__global__ void __launch_bounds__(256) k3_final(float* __restrict__ out, int out_size)
{
    const int idx = blockIdx.x * 256 + threadIdx.x;
    if (idx < NF) {
        const int row = idx >> 7;
        float p = g_part[idx] + g_part[NF + idx];
        float d = g_degp[row] + g_degp[Nn + row];
        float v = p / d;
        out[idx] = v > 0.0f ? v : expm1f(v);
    }
    if (blockIdx.x == 0 && threadIdx.x < 32) {
        float q = g_qpart[threadIdx.x] + g_qpart[threadIdx.x + 32] +
                  g_qpart[threadIdx.x + 64] + g_qpart[threadIdx.x + 96];
        #pragma unroll
        for (int o = 16; o > 0; o >>= 1) q += __shfl_xor_sync(0xffffffffu, q, o);
        if (threadIdx.x == 0 && out_size > NF) out[NF] = q;
    }
}

// ---------------- launch ----------------
extern "C" void kernel_launch(void* const* d_in, const int* in_sizes, int n_in,
                              void* d_out, int out_size) {
    const float* x   = (const float*)d_in[0];
    const int*   adj = (const int*)  d_in[1];
    const float* W   = (const float*)d_in[2];
    const float* w1  = (const float*)d_in[3];
    const float* b1  = (const float*)d_in[4];
    const float* w21 = (const float*)d_in[5];
    const float* b21 = (const float*)d_in[6];
    const float* w22 = (const float*)d_in[7];
    const float* b22 = (const float*)d_in[8];
    float* out = (float*)d_out;

    cudaFuncSetAttribute(k1_feat,  cudaFuncAttributeMaxDynamicSharedMemorySize, K1_SMEM);
    cudaFuncSetAttribute(k1b_quant,cudaFuncAttributeMaxDynamicSharedMemorySize, K1B_SMEM);
    cudaFuncSetAttribute(k2_aggr,  cudaFuncAttributeMaxDynamicSharedMemorySize, K2_SMEM);

    k0_init<<<1, 128>>>();
    k1_feat<<<Nn / 64, 512, K1_SMEM>>>(x, W, w1, b1, w21, b21, w22, b22);
    k1b_quant<<<Nn / 64, 512, K1B_SMEM>>>();
    k2_aggr<<<128, 512, K2_SMEM>>>(adj);
    k3_final<<<(NF + 255) / 256, 256>>>(out, out_size);
}

// round 6
// speedup vs baseline: 1.4088x; 1.4088x over previous
#include <cuda_runtime.h>
#include <cuda_bf16.h>
#include <stdint.h>

#define Nn   8192
#define FIN  512
#define FOUT 128
#define HID  16
#define NF   (Nn*FOUT)

// ---------------- scratch (device globals: allocation-free) ----------------
__device__ __nv_bfloat16 g_hT_hi[FOUT * Nn];   // [128][8192] bf16 limb1, 2MB
__device__ __nv_bfloat16 g_hT_lo[FOUT * Nn];   // limb2, 2MB
__device__ float g_part[2 * NF];               // K-split partial sums
__device__ float g_degp[2 * Nn];               // K-split partial degrees
__device__ float g_qpart[128];                 // per-block qmp partials

// ---------------- PTX helpers ----------------
__device__ __forceinline__ uint32_t smem_u32(const void* p) {
    uint32_t a;
    asm("{ .reg .u64 t; cvta.to.shared.u64 t, %1; cvt.u32.u64 %0, t; }" : "=r"(a) : "l"(p));
    return a;
}
#define CP16(dst, src) \
    asm volatile("cp.async.cg.shared.global [%0], [%1], 16;" :: "r"(dst), "l"(src) : "memory")
#define CP_COMMIT() asm volatile("cp.async.commit_group;" ::: "memory")
#define CP_WAIT1()  asm volatile("cp.async.wait_group 1;" ::: "memory")

#define LDSM4(r0, r1, r2, r3, addr) \
    asm volatile("ldmatrix.sync.aligned.m8n8.x4.shared.b16 {%0,%1,%2,%3},[%4];" \
        : "=r"(r0), "=r"(r1), "=r"(r2), "=r"(r3) : "r"(addr))

#define MMA16816(acc, a, b0, b1) \
    asm volatile("mma.sync.aligned.m16n8k16.row.col.f32.bf16.bf16.f32 " \
        "{%0,%1,%2,%3},{%4,%5,%6,%7},{%8,%9},{%0,%1,%2,%3};" \
        : "+f"((acc)[0]), "+f"((acc)[1]), "+f"((acc)[2]), "+f"((acc)[3]) \
        : "r"((a)[0]), "r"((a)[1]), "r"((a)[2]), "r"((a)[3]), "r"(b0), "r"(b1))

__device__ __forceinline__ uint32_t cvt01(int x, int y) {   // 2x int{0,1} -> bf16x2
    return (x ? 0x3F80u : 0u) | (y ? 0x3F800000u : 0u);
}

// ---------------- kernel 1: h = x@W, emit transposed bf16 hi/lo, qmp -------
// smem: xs[64][36] @0 (9216B); ws[32][132] @9216 (16896B); v1s[16][128] @26112
// (8192B); sml @34304 (256B); h_s[64][133] @34560 (34048B)
#define K1_SMEM 68608

__global__ void __launch_bounds__(512) k1_feat(
    const float* __restrict__ x, const float* __restrict__ W,
    const float* __restrict__ w1, const float* __restrict__ b1,
    const float* __restrict__ w21, const float* __restrict__ b21,
    const float* __restrict__ w22, const float* __restrict__ b22)
{
    extern __shared__ __align__(16) char sm1[];
    float* xs  = (float*)sm1;
    float* ws  = (float*)(sm1 + 9216);
    float* v1s = (float*)(sm1 + 26112);
    float* sml = (float*)(sm1 + 34304);
    float* h_s = (float*)(sm1 + 34560);

    const int t  = threadIdx.x;
    const int m0 = blockIdx.x * 64;

    for (int i = t; i < HID * FOUT; i += 512) {
        int hh = i >> 7, c = i & 127;
        v1s[i] = w1[hh * 256 + c] + w1[hh * 256 + 128 + c];
    }
    if (t < 16) { sml[t] = b1[t]; sml[16 + t] = w21[t]; sml[32 + t] = w22[t]; }
    if (t == 0) { sml[48] = b21[0]; sml[49] = b22[0]; }

    const int r0 = (t >> 4) << 1;      // 2 rows per thread
    const int cb = (t & 15) << 1;
    unsigned long long acc[2][4];
    #pragma unroll
    for (int i = 0; i < 2; i++)
        #pragma unroll
        for (int j = 0; j < 4; j++) acc[i][j] = 0ull;

    for (int kc = 0; kc < 16; kc++) {
        const int k0i = kc * 32;
        {   // xs: 64x32 floats = 512 float4
            int rr = t >> 3, g = t & 7;
            *(float4*)&xs[rr * 36 + g * 4] =
                *(const float4*)&x[(size_t)(m0 + rr) * FIN + k0i + g * 4];
        }
        #pragma unroll
        for (int i = 0; i < 2; i++) {   // ws: 32x128 = 1024 float4
            int item = t + 512 * i;
            int kk = item >> 5, cg = (item & 31) << 2;
            *(float4*)&ws[kk * 132 + cg] =
                *(const float4*)&W[(size_t)(k0i + kk) * FOUT + cg];
        }
        __syncthreads();
        #pragma unroll 8
        for (int kk = 0; kk < 32; kk++) {
            unsigned long long aa[2];
            #pragma unroll
            for (int i = 0; i < 2; i++) {
                float a = xs[(r0 + i) * 36 + kk];
                asm("mov.b64 %0, {%1, %1};" : "=l"(aa[i]) : "r"(__float_as_uint(a)));
            }
            #pragma unroll
            for (int j = 0; j < 4; j++) {
                unsigned long long bp = *(const unsigned long long*)&ws[kk * 132 + cb + 32 * j];
                #pragma unroll
                for (int i = 0; i < 2; i++)
                    asm("fma.rn.f32x2 %0, %1, %2, %0;" : "+l"(acc[i][j]) : "l"(aa[i]), "l"(bp));
            }
        }
        __syncthreads();
    }
    #pragma unroll
    for (int i = 0; i < 2; i++)
        #pragma unroll
        for (int j = 0; j < 4; j++) {
            uint32_t lo, hi;
            asm("mov.b64 {%0, %1}, %2;" : "=r"(lo), "=r"(hi) : "l"(acc[i][j]));
            h_s[(r0 + i) * 133 + cb + 32 * j]     = __uint_as_float(lo);
            h_s[(r0 + i) * 133 + cb + 32 * j + 1] = __uint_as_float(hi);
        }
    __syncthreads();

    // transposed bf16 hi/lo emit: hT[n][m0+r]
    #pragma unroll
    for (int ii = 0; ii < 2; ii++) {
        int item = t + 512 * ii;               // 0..1023
        int n = item >> 3, g = item & 7;       // feature col, 8-row group
        uint32_t hp[4], lp[4];
        #pragma unroll
        for (int q2 = 0; q2 < 4; q2++) {
            float v0 = h_s[(g * 8 + 2 * q2) * 133 + n];
            float v1v = h_s[(g * 8 + 2 * q2 + 1) * 133 + n];
            __nv_bfloat16 h0 = __float2bfloat16(v0), h1 = __float2bfloat16(v1v);
            float l0 = v0 - __bfloat162float(h0), l1 = v1v - __bfloat162float(h1);
            __nv_bfloat16 lb0 = __float2bfloat16(l0), lb1 = __float2bfloat16(l1);
            hp[q2] = (uint32_t)__bfloat16_as_ushort(h0) | ((uint32_t)__bfloat16_as_ushort(h1) << 16);
            lp[q2] = (uint32_t)__bfloat16_as_ushort(lb0) | ((uint32_t)__bfloat16_as_ushort(lb1) << 16);
        }
        size_t off = (size_t)n * Nn + m0 + g * 8;
        *(uint4*)((char*)g_hT_hi + off * 2) = make_uint4(hp[0], hp[1], hp[2], hp[3]);
        *(uint4*)((char*)g_hT_lo + off * 2) = make_uint4(lp[0], lp[1], lp[2], lp[3]);
    }

    // qmp partials: 16 warps x 4 rows
    const int w = t >> 5, l = t & 31;
    float contrib = 0.0f;
    for (int rr = w * 4; rr < w * 4 + 4; rr++) {
        float hv0 = h_s[rr * 133 + l];
        float hv1 = h_s[rr * 133 + l + 32];
        float hv2 = h_s[rr * 133 + l + 64];
        float hv3 = h_s[rr * 133 + l + 96];
        float mu = 0.0f, lv = 0.0f;
        #pragma unroll
        for (int hh = 0; hh < 16; hh++) {
            const float* vr = &v1s[hh * 128];
            float s = hv0 * vr[l] + hv1 * vr[l + 32] + hv2 * vr[l + 64] + hv3 * vr[l + 96];
            #pragma unroll
            for (int o = 16; o > 0; o >>= 1) s += __shfl_xor_sync(0xffffffffu, s, o);
            float u = s + sml[hh];
            u = u > 0.0f ? u : 0.0f;
            mu += u * sml[16 + hh];
            lv += u * sml[32 + hh];
        }
        if (l == 0) {
            mu += sml[48]; lv += sml[49];
            float sig = (lv > 20.0f) ? lv : log1pf(expf(lv));
            contrib += 0.5f * mu * mu - logf(sig);
        }
    }
    __syncthreads();
    if (l == 0) xs[w] = contrib;
    __syncthreads();
    if (t == 0) {
        float s = 0.0f;
        #pragma unroll
        for (int i = 0; i < 16; i++) s += xs[i];
        g_qpart[blockIdx.x] = s;
    }
}

// ---------------- kernel 2: masked aggregation, 2-limb bf16 HMMA -----------
// Grid 128: CTA (mt, ksp): rows [mt*128,+128), K-half [ksp*4096,+4096).
// Buffer: A int32 [128][68] pad->272B (34816B) | Bh bf16 [128][72] (18432B) | Bl (18432B)
#define ASTRIDE 272
#define OFF_BH  34816
#define OFF_BL  53248
#define BUFSZ   71680
#define K2_SMEM (2*BUFSZ)
#define NCH2    64

__global__ void __launch_bounds__(512, 1) k2_aggr(const int* __restrict__ adj)
{
    extern __shared__ __align__(128) char sm2[];
    const uint32_t sb = smem_u32(sm2);
    const int t = threadIdx.x;
    const int mt = blockIdx.x >> 1, ksp = blockIdx.x & 1;
    const int m0 = mt * 128;
    const int kbase = ksp * 4096;

    const int w = t >> 5, l = t & 31;
    const int wm = w & 3, wn = w >> 2;     // 4x4 warps, warp tile 32 rows x 32 cols

    // loader indexing: 4 threads per row
    const int lr = t >> 2, lq = t & 3;
    const char* aSrc = (const char*)(adj + (size_t)(m0 + lr) * Nn + kbase + lq * 16);
    const char* hSrc = (const char*)(g_hT_hi + (size_t)lr * Nn + kbase + lq * 16);
    const char* lSrc = (const char*)(g_hT_lo + (size_t)lr * Nn + kbase + lq * 16);
    const uint32_t aDst = sb + lr * ASTRIDE + lq * 64;
    const uint32_t hDst = sb + OFF_BH + lr * 144 + lq * 32;
    const uint32_t lDst = sb + OFF_BL + lr * 144 + lq * 32;

#define LOAD_CHUNK(c, buf) do {                                                \
    const char* _as = aSrc + (size_t)(c) * 256;                                \
    const char* _hs = hSrc + (size_t)(c) * 128;                                \
    const char* _ls = lSrc + (size_t)(c) * 128;                                \
    uint32_t _ad = aDst + (buf) * BUFSZ;                                       \
    uint32_t _hd = hDst + (buf) * BUFSZ;                                       \
    uint32_t _ld = lDst + (buf) * BUFSZ;                                       \
    CP16(_ad,      _as);      CP16(_ad + 16, _as + 16);                        \
    CP16(_ad + 32, _as + 32); CP16(_ad + 48, _as + 48);                        \
    CP16(_hd, _hs);           CP16(_hd + 16, _hs + 16);                        \
    CP16(_ld, _ls);           CP16(_ld + 16, _ls + 16);                        \
} while (0)

    float acc[2][4][4];
    #pragma unroll
    for (int m = 0; m < 2; m++)
        #pragma unroll
        for (int j = 0; j < 4; j++)
            #pragma unroll
            for (int q = 0; q < 4; q++) acc[m][j][q] = 0.0f;
    int da[2][2] = {{0, 0}, {0, 0}};

    LOAD_CHUNK(0, 0); CP_COMMIT();
    LOAD_CHUNK(1, 1); CP_COMMIT();

    // B ldmatrix lane addressing (R4-proven mapping)
    const int bn_lane = (l & 7) | ((l >> 4) << 3);
    const int bc_lane = ((l >> 3) & 1) << 3;
    const int arow = wm * 32 + (l >> 2);
    const int acol = 2 * (l & 3);

    for (int c = 0; c < NCH2; c++) {
        CP_WAIT1();
        __syncthreads();
        const int buf = c & 1;
        const char* smA = sm2 + buf * BUFSZ;
        const uint32_t bhB = sb + buf * BUFSZ + OFF_BH;
        const uint32_t blB = sb + buf * BUFSZ + OFF_BL;

        #pragma unroll
        for (int kk = 0; kk < 64; kk += 16) {
            uint32_t a[2][4];
            #pragma unroll
            for (int m = 0; m < 2; m++) {
                const int r = arow + m * 16;
                const int cc = kk + acol;
                int2 v;
                v = *(const int2*)(smA + r * ASTRIDE + cc * 4);
                a[m][0] = cvt01(v.x, v.y); if (wn == 0) da[m][0] += v.x + v.y;
                v = *(const int2*)(smA + (r + 8) * ASTRIDE + cc * 4);
                a[m][1] = cvt01(v.x, v.y); if (wn == 0) da[m][1] += v.x + v.y;
                v = *(const int2*)(smA + r * ASTRIDE + (cc + 8) * 4);
                a[m][2] = cvt01(v.x, v.y); if (wn == 0) da[m][0] += v.x + v.y;
                v = *(const int2*)(smA + (r + 8) * ASTRIDE + (cc + 8) * 4);
                a[m][3] = cvt01(v.x, v.y); if (wn == 0) da[m][1] += v.x + v.y;
            }
            #pragma unroll
            for (int n16 = 0; n16 < 2; n16++) {
                const int n = wn * 32 + n16 * 16 + bn_lane;
                const uint32_t boff = n * 144 + (kk + bc_lane) * 2;
                uint32_t b0, b1, b2, b3;
                LDSM4(b0, b1, b2, b3, bhB + boff);
                MMA16816(acc[0][2 * n16],     a[0], b0, b1);
                MMA16816(acc[0][2 * n16 + 1], a[0], b2, b3);
                MMA16816(acc[1][2 * n16],     a[1], b0, b1);
                MMA16816(acc[1][2 * n16 + 1], a[1], b2, b3);
                LDSM4(b0, b1, b2, b3, blB + boff);
                MMA16816(acc[0][2 * n16],     a[0], b0, b1);
                MMA16816(acc[0][2 * n16 + 1], a[0], b2, b3);
                MMA16816(acc[1][2 * n16],     a[1], b0, b1);
                MMA16816(acc[1][2 * n16 + 1], a[1], b2, b3);
            }
        }
        __syncthreads();
        if (c + 2 < NCH2) LOAD_CHUNK(c + 2, buf);
        CP_COMMIT();
    }
#undef LOAD_CHUNK

    // epilogue: K-split partials
    float* slab = g_part + (size_t)ksp * NF;
    #pragma unroll
    for (int m = 0; m < 2; m++) {
        const int row = m0 + wm * 32 + m * 16 + (l >> 2);
        #pragma unroll
        for (int j = 0; j < 4; j++) {
            const int col = wn * 32 + j * 8 + 2 * (l & 3);
            *(float2*)&slab[(size_t)row * FOUT + col] =
                make_float2(acc[m][j][0], acc[m][j][1]);
            *(float2*)&slab[(size_t)(row + 8) * FOUT + col] =
                make_float2(acc[m][j][2], acc[m][j][3]);
        }
    }
    if (wn == 0) {
        #pragma unroll
        for (int m = 0; m < 2; m++) {
            int d0 = da[m][0], d1 = da[m][1];
            d0 += __shfl_xor_sync(0xffffffffu, d0, 1);
            d0 += __shfl_xor_sync(0xffffffffu, d0, 2);
            d1 += __shfl_xor_sync(0xffffffffu, d1, 1);
            d1 += __shfl_xor_sync(0xffffffffu, d1, 2);
            if ((l & 3) == 0) {
                const int row = m0 + wm * 32 + m * 16 + (l >> 2);
                g_degp[ksp * Nn + row]     = (float)d0;
                g_degp[ksp * Nn + row + 8] = (float)d1;
            }
        }
    }
}

// ---------------- kernel 3: combine K-halves, scale, elu, qmp --------------
__global__ void __launch_bounds__(256) k3_final(float* __restrict__ out, int out_size)
{
    const int idx = blockIdx.x * 256 + threadIdx.x;
    if (idx < NF) {
        const int row = idx >> 7;
        float p = g_part[idx] + g_part[NF + idx];
        float d = g_degp[row] + g_degp[Nn + row];
        float v = p / d;
        out[idx] = v > 0.0f ? v : expm1f(v);
    }
    if (blockIdx.x == 0 && threadIdx.x < 32) {
        float q = g_qpart[threadIdx.x] + g_qpart[threadIdx.x + 32] +
                  g_qpart[threadIdx.x + 64] + g_qpart[threadIdx.x + 96];
        #pragma unroll
        for (int o = 16; o > 0; o >>= 1) q += __shfl_xor_sync(0xffffffffu, q, o);
        if (threadIdx.x == 0 && out_size > NF) out[NF] = q;
    }
}

// ---------------- launch ----------------
extern "C" void kernel_launch(void* const* d_in, const int* in_sizes, int n_in,
                              void* d_out, int out_size) {
    const float* x   = (const float*)d_in[0];
    const int*   adj = (const int*)  d_in[1];
    const float* W   = (const float*)d_in[2];
    const float* w1  = (const float*)d_in[3];
    const float* b1  = (const float*)d_in[4];
    const float* w21 = (const float*)d_in[5];
    const float* b21 = (const float*)d_in[6];
    const float* w22 = (const float*)d_in[7];
    const float* b22 = (const float*)d_in[8];
    float* out = (float*)d_out;

    cudaFuncSetAttribute(k1_feat, cudaFuncAttributeMaxDynamicSharedMemorySize, K1_SMEM);
    cudaFuncSetAttribute(k2_aggr, cudaFuncAttributeMaxDynamicSharedMemorySize, K2_SMEM);

    k1_feat<<<Nn / 64, 512, K1_SMEM>>>(x, W, w1, b1, w21, b21, w22, b22);
    k2_aggr<<<128, 512, K2_SMEM>>>(adj);
    k3_final<<<(NF + 255) / 256, 256>>>(out, out_size);
}

// round 7
// speedup vs baseline: 2.4399x; 1.7319x over previous
#include <cuda_runtime.h>
#include <cuda_fp16.h>
#include <stdint.h>

#define Nn   8192
#define FIN  512
#define FOUT 128
#define HID  16
#define NF   (Nn*FOUT)

// ---------------- scratch (device globals: allocation-free) ----------------
__device__ __half g_hT[FOUT * Nn];     // h transposed, fp16, [feat][node], 2MB
__device__ float  g_qpart[128];        // per-block qmp partials

// ---------------- PTX helpers ----------------
__device__ __forceinline__ uint32_t smem_u32(const void* p) {
    uint32_t a;
    asm("{ .reg .u64 t; cvta.to.shared.u64 t, %1; cvt.u32.u64 %0, t; }" : "=r"(a) : "l"(p));
    return a;
}
#define CP16(dst, src) \
    asm volatile("cp.async.cg.shared.global [%0], [%1], 16;" :: "r"(dst), "l"(src) : "memory")
#define CP_COMMIT() asm volatile("cp.async.commit_group;" ::: "memory")
#define CP_WAIT1()  asm volatile("cp.async.wait_group 1;" ::: "memory")

#define LDSM4(r0, r1, r2, r3, addr) \
    asm volatile("ldmatrix.sync.aligned.m8n8.x4.shared.b16 {%0,%1,%2,%3},[%4];" \
        : "=r"(r0), "=r"(r1), "=r"(r2), "=r"(r3) : "r"(addr))

#define MMAH(acc, a0, a1, a2, a3, b0, b1) \
    asm volatile("mma.sync.aligned.m16n8k16.row.col.f32.f16.f16.f32 " \
        "{%0,%1,%2,%3},{%4,%5,%6,%7},{%8,%9},{%0,%1,%2,%3};" \
        : "+f"((acc)[0]), "+f"((acc)[1]), "+f"((acc)[2]), "+f"((acc)[3]) \
        : "r"(a0), "r"(a1), "r"(a2), "r"(a3), "r"(b0), "r"(b1))

#define STS128(addr, v) \
    asm volatile("st.shared.v4.b32 [%0], {%1, %2, %3, %4};" \
                 :: "r"(addr), "r"((v).x), "r"((v).y), "r"((v).z), "r"((v).w) : "memory")

__device__ __forceinline__ uint32_t pkh(int x, int y) {   // 2x int{0,1} -> fp16x2
    return (x ? 0x3C00u : 0u) | (y ? 0x3C000000u : 0u);
}

// ---------------- kernel 1: h = x@W, emit transposed fp16, qmp -------------
// smem: xs[64][36] @0 (9216B); ws[32][132] @9216 (16896B); v1s[16][128] @26112
// (8192B); sml @34304 (256B); h_s[64][133] @34560 (34048B)
#define K1_SMEM 68608

__global__ void __launch_bounds__(256) k1_feat(
    const float* __restrict__ x, const float* __restrict__ W,
    const float* __restrict__ w1, const float* __restrict__ b1,
    const float* __restrict__ w21, const float* __restrict__ b21,
    const float* __restrict__ w22, const float* __restrict__ b22)
{
    extern __shared__ __align__(16) char sm1[];
    float* xs  = (float*)sm1;
    float* ws  = (float*)(sm1 + 9216);
    float* v1s = (float*)(sm1 + 26112);
    float* sml = (float*)(sm1 + 34304);
    float* h_s = (float*)(sm1 + 34560);

    const int t  = threadIdx.x;
    const int m0 = blockIdx.x * 64;

    for (int i = t; i < HID * FOUT; i += 256) {
        int hh = i >> 7, c = i & 127;
        v1s[i] = w1[hh * 256 + c] + w1[hh * 256 + 128 + c];
    }
    if (t < 16) { sml[t] = b1[t]; sml[16 + t] = w21[t]; sml[32 + t] = w22[t]; }
    if (t == 0) { sml[48] = b21[0]; sml[49] = b22[0]; }

    const int r0 = (t >> 4) << 2;      // 4 rows per thread
    const int cb = (t & 15) << 1;      // col pair base
    unsigned long long acc[4][4];
    #pragma unroll
    for (int i = 0; i < 4; i++)
        #pragma unroll
        for (int j = 0; j < 4; j++) acc[i][j] = 0ull;

    for (int kc = 0; kc < 16; kc++) {
        const int k0i = kc * 32;
        #pragma unroll
        for (int i = 0; i < 2; i++) {
            int item = t + 256 * i;
            int rr = item >> 3, g = item & 7;
            *(float4*)&xs[rr * 36 + g * 4] =
                *(const float4*)&x[(size_t)(m0 + rr) * FIN + k0i + g * 4];
        }
        #pragma unroll
        for (int i = 0; i < 4; i++) {
            int item = t + 256 * i;
            int kk = item >> 5, cg = (item & 31) << 2;
            *(float4*)&ws[kk * 132 + cg] =
                *(const float4*)&W[(size_t)(k0i + kk) * FOUT + cg];
        }
        __syncthreads();
        #pragma unroll 8
        for (int kk = 0; kk < 32; kk++) {
            unsigned long long aa[4];
            #pragma unroll
            for (int i = 0; i < 4; i++) {
                float a = xs[(r0 + i) * 36 + kk];
                asm("mov.b64 %0, {%1, %1};" : "=l"(aa[i]) : "r"(__float_as_uint(a)));
            }
            #pragma unroll
            for (int j = 0; j < 4; j++) {
                unsigned long long bp = *(const unsigned long long*)&ws[kk * 132 + cb + 32 * j];
                #pragma unroll
                for (int i = 0; i < 4; i++)
                    asm("fma.rn.f32x2 %0, %1, %2, %0;" : "+l"(acc[i][j]) : "l"(aa[i]), "l"(bp));
            }
        }
        __syncthreads();
    }
    #pragma unroll
    for (int i = 0; i < 4; i++)
        #pragma unroll
        for (int j = 0; j < 4; j++) {
            uint32_t lo, hi;
            asm("mov.b64 {%0, %1}, %2;" : "=r"(lo), "=r"(hi) : "l"(acc[i][j]));
            h_s[(r0 + i) * 133 + cb + 32 * j]     = __uint_as_float(lo);
            h_s[(r0 + i) * 133 + cb + 32 * j + 1] = __uint_as_float(hi);
        }
    __syncthreads();

    // transposed fp16 emit: hT[n][m0+r], single limb
    #pragma unroll
    for (int ii = 0; ii < 4; ii++) {
        int item = t + 256 * ii;               // 0..1023
        int n = item >> 3, g = item & 7;       // feature col, 8-row group
        uint32_t hp[4];
        #pragma unroll
        for (int q2 = 0; q2 < 4; q2++) {
            float v0 = h_s[(g * 8 + 2 * q2) * 133 + n];
            float v1 = h_s[(g * 8 + 2 * q2 + 1) * 133 + n];
            __half h0 = __float2half_rn(v0), h1 = __float2half_rn(v1);
            hp[q2] = (uint32_t)__half_as_ushort(h0) | ((uint32_t)__half_as_ushort(h1) << 16);
        }
        size_t off = (size_t)n * Nn + m0 + g * 8;
        *(uint4*)((char*)g_hT + off * 2) = make_uint4(hp[0], hp[1], hp[2], hp[3]);
    }

    // qmp partials: 8 warps x 8 rows
    const int w = t >> 5, l = t & 31;
    float contrib = 0.0f;
    for (int rr = w * 8; rr < w * 8 + 8; rr++) {
        float hv0 = h_s[rr * 133 + l];
        float hv1 = h_s[rr * 133 + l + 32];
        float hv2 = h_s[rr * 133 + l + 64];
        float hv3 = h_s[rr * 133 + l + 96];
        float mu = 0.0f, lv = 0.0f;
        #pragma unroll
        for (int hh = 0; hh < 16; hh++) {
            const float* vr = &v1s[hh * 128];
            float s = hv0 * vr[l] + hv1 * vr[l + 32] + hv2 * vr[l + 64] + hv3 * vr[l + 96];
            #pragma unroll
            for (int o = 16; o > 0; o >>= 1) s += __shfl_xor_sync(0xffffffffu, s, o);
            float u = s + sml[hh];
            u = u > 0.0f ? u : 0.0f;
            mu += u * sml[16 + hh];
            lv += u * sml[32 + hh];
        }
        if (l == 0) {
            mu += sml[48]; lv += sml[49];
            float sig = (lv > 20.0f) ? lv : log1pf(expf(lv));
            contrib += 0.5f * mu * mu - logf(sig);
        }
    }
    __syncthreads();
    if (l == 0) sml[56 + w] = contrib;
    __syncthreads();
    if (t == 0) {
        float s = 0.0f;
        #pragma unroll
        for (int i = 0; i < 8; i++) s += sml[56 + i];
        g_qpart[blockIdx.x] = s;
    }
}

// ---------------- kernel 2: masked aggregation, single-pass fp16 HMMA ------
// Grid 128: CTA = rows [blk*64, +64), N=128, K=8192 (128 chunks of 64).
// Buffer: A fp16 [64][72] (9216B) | B fp16 [128][72] (18432B); double-buffered.
#define ASTR   144
#define OFF_B  9216
#define BUFSZ  27648
#define NCH2   128
#define K2_SMEM (2*BUFSZ + 256)

__global__ void __launch_bounds__(512, 1) k2_aggr(
    const int* __restrict__ adj, float* __restrict__ out, int out_size)
{
    extern __shared__ __align__(128) char sm2[];
    const uint32_t sb = smem_u32(sm2);
    float* sdeg = (float*)(sm2 + 2 * BUFSZ);
    const int t = threadIdx.x;
    const int w = t >> 5, l = t & 31;
    const int wm = w & 3, wn = w >> 2;     // 4x4 warps; warp tile 16 rows x 32 cols
    const int m0 = blockIdx.x * 64;

    // qmp scalar (k1 partials), block 0 only
    if (blockIdx.x == 0 && t < 32) {
        float q = g_qpart[t] + g_qpart[t + 32] + g_qpart[t + 64] + g_qpart[t + 96];
        #pragma unroll
        for (int o = 16; o > 0; o >>= 1) q += __shfl_xor_sync(0xffffffffu, q, o);
        if (t == 0 && out_size > NF) out[NF] = q;
    }

    // ---- loader indexing ----
    const int lr  = t >> 3;                 // A row 0..63 (8 threads/row)
    const int lq8 = (t & 7) * 8;            // 8 ints per thread
    const int* aSrc = adj + (size_t)(m0 + lr) * Nn + lq8;
    const uint32_t aDst = sb + lr * ASTR + lq8 * 2;
    const int bn   = t >> 2;                // B feat row 0..127 (4 threads/row)
    const int bseg = t & 3;
    const __half* bSrc = g_hT + (size_t)bn * Nn + bseg * 16;
    const uint32_t bDst = sb + OFF_B + bn * ASTR + bseg * 32;

    int4 rA0, rA1;
    int dacc = 0;

#define LDA(c) do { \
    rA0 = *(const int4*)(aSrc + (size_t)(c) * 64); \
    rA1 = *(const int4*)(aSrc + (size_t)(c) * 64 + 4); } while (0)
#define STA(buf) do { \
    dacc += rA0.x + rA0.y + rA0.z + rA0.w + rA1.x + rA1.y + rA1.z + rA1.w; \
    uint4 p; \
    p.x = pkh(rA0.x, rA0.y); p.y = pkh(rA0.z, rA0.w); \
    p.z = pkh(rA1.x, rA1.y); p.w = pkh(rA1.z, rA1.w); \
    STS128(aDst + (buf) * BUFSZ, p); } while (0)
#define CPB(c, buf) do { \
    const char* _s = (const char*)(bSrc + (size_t)(c) * 64); \
    uint32_t _d = bDst + (buf) * BUFSZ; \
    CP16(_d, _s); CP16(_d + 16, _s + 16); } while (0)

    float acc[4][4];
    #pragma unroll
    for (int j = 0; j < 4; j++)
        #pragma unroll
        for (int q = 0; q < 4; q++) acc[j][q] = 0.0f;

    // prologue
    LDA(0);
    CPB(0, 0); CP_COMMIT();
    CPB(1, 1); CP_COMMIT();
    STA(0);
    LDA(1);

    // fragment addressing (lane constants)
    const uint32_t aLane = sb + (wm * 16 + (l & 15)) * ASTR + ((l >> 4) * 8) * 2;
    const int bn_lane = (l & 7) | ((l >> 4) << 3);
    const int bc_lane = ((l >> 3) & 1) << 3;
    const uint32_t bLane0 = sb + OFF_B + (wn * 32 + bn_lane) * ASTR + bc_lane * 2;
    const uint32_t bLane1 = bLane0 + 16 * ASTR;

    for (int c = 0; c < NCH2; c++) {
        CP_WAIT1();                    // B(c) arrived
        __syncthreads();               // A(c) visible; prev compute done
        const int buf = c & 1;
        if (c + 1 < NCH2) STA(buf ^ 1);       // stage A(c+1) into other buffer
        if (c + 2 < NCH2) LDA(c + 2);

        const uint32_t aB  = aLane  + buf * BUFSZ;
        const uint32_t bB0 = bLane0 + buf * BUFSZ;
        const uint32_t bB1 = bLane1 + buf * BUFSZ;
        #pragma unroll
        for (int kk = 0; kk < 64; kk += 16) {
            uint32_t a0, a1, a2, a3, b0, b1, b2, b3;
            LDSM4(a0, a1, a2, a3, aB + kk * 2);
            LDSM4(b0, b1, b2, b3, bB0 + kk * 2);
            MMAH(acc[0], a0, a1, a2, a3, b0, b1);
            MMAH(acc[1], a0, a1, a2, a3, b2, b3);
            LDSM4(b0, b1, b2, b3, bB1 + kk * 2);
            MMAH(acc[2], a0, a1, a2, a3, b0, b1);
            MMAH(acc[3], a0, a1, a2, a3, b2, b3);
        }
        __syncthreads();               // all warps done with B(c) region
        if (c + 2 < NCH2) CPB(c + 2, buf);
        CP_COMMIT();                   // always commit (possibly empty group)
    }
#undef LDA
#undef STA
#undef CPB

    // ---- degrees: reduce over the 8 loader threads per row ----
    dacc += __shfl_xor_sync(0xffffffffu, dacc, 1);
    dacc += __shfl_xor_sync(0xffffffffu, dacc, 2);
    dacc += __shfl_xor_sync(0xffffffffu, dacc, 4);
    if ((l & 7) == 0) sdeg[w * 4 + (l >> 3)] = (float)dacc;
    __syncthreads();

    // ---- epilogue: scale by 1/deg, elu, write out ----
    const int r = wm * 16 + (l >> 2);
    const float d0 = sdeg[r], d8 = sdeg[r + 8];
    const float inv0 = d0 > 0.0f ? 1.0f / d0 : 0.0f;
    const float inv8 = d8 > 0.0f ? 1.0f / d8 : 0.0f;
    #pragma unroll
    for (int j = 0; j < 4; j++) {
        const int col = wn * 32 + j * 8 + 2 * (l & 3);
        float v0 = acc[j][0] * inv0, v1 = acc[j][1] * inv0;
        float v2 = acc[j][2] * inv8, v3 = acc[j][3] * inv8;
        v0 = v0 > 0.0f ? v0 : expm1f(v0);
        v1 = v1 > 0.0f ? v1 : expm1f(v1);
        v2 = v2 > 0.0f ? v2 : expm1f(v2);
        v3 = v3 > 0.0f ? v3 : expm1f(v3);
        *(float2*)&out[(size_t)(m0 + r) * FOUT + col]     = make_float2(v0, v1);
        *(float2*)&out[(size_t)(m0 + r + 8) * FOUT + col] = make_float2(v2, v3);
    }
}

// ---------------- launch ----------------
extern "C" void kernel_launch(void* const* d_in, const int* in_sizes, int n_in,
                              void* d_out, int out_size) {
    const float* x   = (const float*)d_in[0];
    const int*   adj = (const int*)  d_in[1];
    const float* W   = (const float*)d_in[2];
    const float* w1  = (const float*)d_in[3];
    const float* b1  = (const float*)d_in[4];
    const float* w21 = (const float*)d_in[5];
    const float* b21 = (const float*)d_in[6];
    const float* w22 = (const float*)d_in[7];
    const float* b22 = (const float*)d_in[8];
    float* out = (float*)d_out;

    cudaFuncSetAttribute(k1_feat, cudaFuncAttributeMaxDynamicSharedMemorySize, K1_SMEM);
    cudaFuncSetAttribute(k2_aggr, cudaFuncAttributeMaxDynamicSharedMemorySize, K2_SMEM);

    k1_feat<<<Nn / 64, 256, K1_SMEM>>>(x, W, w1, b1, w21, b21, w22, b22);
    k2_aggr<<<Nn / 64, 512, K2_SMEM>>>(adj, out, out_size);
}

// round 8
// speedup vs baseline: 3.1007x; 1.2709x over previous
#include <cuda_runtime.h>
#include <cuda_fp16.h>
#include <stdint.h>

#define Nn   8192
#define FIN  512
#define FOUT 128
#define HID  16
#define NF   (Nn*FOUT)

// ---------------- scratch (device globals: allocation-free) ----------------
__device__ __half g_xh[Nn * FIN];      // x hi limb fp16, 8MB
__device__ __half g_xl[Nn * FIN];      // x lo limb
__device__ __half g_wh[FOUT * FIN];    // W^T hi limb [n][k]
__device__ __half g_wl[FOUT * FIN];    // W^T lo limb
__device__ __half g_hT[FOUT * Nn];     // h transposed fp16 [feat][node], 2MB
__device__ float  g_part[2 * NF];      // K-split partial sums, 8MB
__device__ float  g_degp[2 * Nn];      // K-split partial degrees
__device__ float  g_qpart[128];        // per-block qmp partials

// ---------------- PTX helpers ----------------
__device__ __forceinline__ uint32_t smem_u32(const void* p) {
    uint32_t a;
    asm("{ .reg .u64 t; cvta.to.shared.u64 t, %1; cvt.u32.u64 %0, t; }" : "=r"(a) : "l"(p));
    return a;
}
#define CP16(dst, src) \
    asm volatile("cp.async.cg.shared.global [%0], [%1], 16;" :: "r"(dst), "l"(src) : "memory")
#define CP_COMMIT() asm volatile("cp.async.commit_group;" ::: "memory")
#define CP_WAIT1()  asm volatile("cp.async.wait_group 1;" ::: "memory")
#define CP_WAIT0()  asm volatile("cp.async.wait_group 0;" ::: "memory")

#define LDSM4(r0, r1, r2, r3, addr) \
    asm volatile("ldmatrix.sync.aligned.m8n8.x4.shared.b16 {%0,%1,%2,%3},[%4];" \
        : "=r"(r0), "=r"(r1), "=r"(r2), "=r"(r3) : "r"(addr))

#define MMAH(acc, a0, a1, a2, a3, b0, b1) \
    asm volatile("mma.sync.aligned.m16n8k16.row.col.f32.f16.f16.f32 " \
        "{%0,%1,%2,%3},{%4,%5,%6,%7},{%8,%9},{%0,%1,%2,%3};" \
        : "+f"((acc)[0]), "+f"((acc)[1]), "+f"((acc)[2]), "+f"((acc)[3]) \
        : "r"(a0), "r"(a1), "r"(a2), "r"(a3), "r"(b0), "r"(b1))

#define STS128(addr, v) \
    asm volatile("st.shared.v4.b32 [%0], {%1, %2, %3, %4};" \
                 :: "r"(addr), "r"((v).x), "r"((v).y), "r"((v).z), "r"((v).w) : "memory")

__device__ __forceinline__ uint32_t pkh(int x, int y) {   // 2x int{0,1} -> fp16x2
    return (x ? 0x3C00u : 0u) | (y ? 0x3C000000u : 0u);
}
__device__ __forceinline__ uint32_t pk2f(float a, float b) {
    __half ha = __float2half_rn(a), hb = __float2half_rn(b);
    return (uint32_t)__half_as_ushort(ha) | ((uint32_t)__half_as_ushort(hb) << 16);
}

// ---------------- kernel 0a: x -> 2-limb fp16 ----------------
__global__ void __launch_bounds__(256) k0_convx(const float* __restrict__ x)
{
    const int i = (blockIdx.x * 256 + threadIdx.x) * 4;
    float4 v = *(const float4*)&x[i];
    __half hx = __float2half_rn(v.x), hy = __float2half_rn(v.y);
    __half hz = __float2half_rn(v.z), hw = __float2half_rn(v.w);
    uint2 hp, lp;
    hp.x = (uint32_t)__half_as_ushort(hx) | ((uint32_t)__half_as_ushort(hy) << 16);
    hp.y = (uint32_t)__half_as_ushort(hz) | ((uint32_t)__half_as_ushort(hw) << 16);
    lp.x = pk2f(v.x - __half2float(hx), v.y - __half2float(hy));
    lp.y = pk2f(v.z - __half2float(hz), v.w - __half2float(hw));
    *(uint2*)&g_xh[i] = hp;
    *(uint2*)&g_xl[i] = lp;
}

// ---------------- kernel 0b: W -> transposed 2-limb fp16 ----------------
__global__ void __launch_bounds__(256) k0_convw(const float* __restrict__ W)
{
    const int idx = blockIdx.x * 256 + threadIdx.x;   // 0..65535
    const int n = idx >> 9, k = idx & 511;
    float v = W[k * FOUT + n];
    __half h = __float2half_rn(v);
    g_wh[idx] = h;
    g_wl[idx] = __float2half_rn(v - __half2float(h));
}

// ---------------- kernel 1: h = x@W via 2-limb fp16 HMMA; hT emit + qmp ----
// smem: A_hi @0 (64x528=33792) | A_lo @33792 | B_hi @67584 (128x528=67584) |
//       B_lo @135168; total 202752. Epilogue overlays: h_s[64][133] @0,
//       v1s @34048, sml @42240.
#define XHO 0
#define XLO 33792
#define WHO 67584
#define WLO 135168
#define K1STR 528
#define K1_SMEM 202752

__global__ void __launch_bounds__(256) k1_gemm(
    const float* __restrict__ w1, const float* __restrict__ b1,
    const float* __restrict__ w21, const float* __restrict__ b21,
    const float* __restrict__ w22, const float* __restrict__ b22)
{
    extern __shared__ __align__(128) char sm1[];
    const uint32_t sb = smem_u32(sm1);
    const int t = threadIdx.x;
    const int w = t >> 5, l = t & 31;
    const int wm = w & 1, wn = w >> 1;     // 2x4 warps; warp tile 32 rows x 32 cols
    const int m0 = blockIdx.x * 64;

    float acc[2][4][4];
    #pragma unroll
    for (int m = 0; m < 2; m++)
        #pragma unroll
        for (int j = 0; j < 4; j++)
            #pragma unroll
            for (int q = 0; q < 4; q++) acc[m][j][q] = 0.0f;

    // lane addressing
    const uint32_t aH = sb + XHO + (wm * 32 + (l & 15)) * K1STR + ((l >> 4) * 8) * 2;
    const uint32_t aL = aH + (XLO - XHO);
    const int bn_lane = (l & 7) | ((l >> 4) << 3);
    const int bc_lane = ((l >> 3) & 1) << 3;
    const uint32_t bH = sb + WHO + (wn * 32 + bn_lane) * K1STR + bc_lane * 2;
    const uint32_t bL = bH + (WLO - WHO);

    for (int ch = 0; ch < 2; ch++) {
        // load chunk: A 64 rows x 256 k (hi+lo), B 128 rows x 256 k (hi+lo)
        for (int i = t; i < 2048; i += 256) {
            int row = i >> 5, seg = i & 31;
            size_t so = ((size_t)(m0 + row) * FIN + ch * 256) * 2 + seg * 16;
            CP16(sb + XHO + row * K1STR + seg * 16, (const char*)g_xh + so);
            CP16(sb + XLO + row * K1STR + seg * 16, (const char*)g_xl + so);
        }
        for (int i = t; i < 4096; i += 256) {
            int row = i >> 5, seg = i & 31;
            size_t so = ((size_t)row * FIN + ch * 256) * 2 + seg * 16;
            CP16(sb + WHO + row * K1STR + seg * 16, (const char*)g_wh + so);
            CP16(sb + WLO + row * K1STR + seg * 16, (const char*)g_wl + so);
        }
        CP_COMMIT();
        CP_WAIT0();
        __syncthreads();

        #pragma unroll 4
        for (int kk = 0; kk < 256; kk += 16) {
            uint32_t ah[2][4], al[2][4];
            LDSM4(ah[0][0], ah[0][1], ah[0][2], ah[0][3], aH + kk * 2);
            LDSM4(ah[1][0], ah[1][1], ah[1][2], ah[1][3], aH + 16 * K1STR + kk * 2);
            LDSM4(al[0][0], al[0][1], al[0][2], al[0][3], aL + kk * 2);
            LDSM4(al[1][0], al[1][1], al[1][2], al[1][3], aL + 16 * K1STR + kk * 2);
            #pragma unroll
            for (int n16 = 0; n16 < 2; n16++) {
                uint32_t bh0, bh1, bh2, bh3, bl0, bl1, bl2, bl3;
                LDSM4(bh0, bh1, bh2, bh3, bH + n16 * 16 * K1STR + kk * 2);
                LDSM4(bl0, bl1, bl2, bl3, bL + n16 * 16 * K1STR + kk * 2);
                #pragma unroll
                for (int m = 0; m < 2; m++) {
                    MMAH(acc[m][2 * n16],     ah[m][0], ah[m][1], ah[m][2], ah[m][3], bh0, bh1);
                    MMAH(acc[m][2 * n16 + 1], ah[m][0], ah[m][1], ah[m][2], ah[m][3], bh2, bh3);
                    MMAH(acc[m][2 * n16],     al[m][0], al[m][1], al[m][2], al[m][3], bh0, bh1);
                    MMAH(acc[m][2 * n16 + 1], al[m][0], al[m][1], al[m][2], al[m][3], bh2, bh3);
                    MMAH(acc[m][2 * n16],     ah[m][0], ah[m][1], ah[m][2], ah[m][3], bl0, bl1);
                    MMAH(acc[m][2 * n16 + 1], ah[m][0], ah[m][1], ah[m][2], ah[m][3], bl2, bl3);
                }
            }
        }
        __syncthreads();
    }

    // ---- epilogue: h tile to smem ----
    float* h_s = (float*)sm1;                 // [64][133]
    float* v1s = (float*)(sm1 + 34048);       // [16][128]
    float* sml = (float*)(sm1 + 42240);
    #pragma unroll
    for (int m = 0; m < 2; m++) {
        const int row = wm * 32 + m * 16 + (l >> 2);
        #pragma unroll
        for (int j = 0; j < 4; j++) {
            const int col = wn * 32 + j * 8 + 2 * (l & 3);
            h_s[row * 133 + col]           = acc[m][j][0];
            h_s[row * 133 + col + 1]       = acc[m][j][1];
            h_s[(row + 8) * 133 + col]     = acc[m][j][2];
            h_s[(row + 8) * 133 + col + 1] = acc[m][j][3];
        }
    }
    for (int i = t; i < HID * FOUT; i += 256) {
        int hh = i >> 7, c = i & 127;
        v1s[i] = w1[hh * 256 + c] + w1[hh * 256 + 128 + c];
    }
    if (t < 16) { sml[t] = b1[t]; sml[16 + t] = w21[t]; sml[32 + t] = w22[t]; }
    if (t == 0) { sml[48] = b21[0]; sml[49] = b22[0]; }
    __syncthreads();

    // transposed fp16 emit: hT[n][m0+r]
    #pragma unroll
    for (int ii = 0; ii < 4; ii++) {
        int item = t + 256 * ii;               // 0..1023
        int n = item >> 3, g = item & 7;       // feature col, 8-row group
        uint32_t hp[4];
        #pragma unroll
        for (int q2 = 0; q2 < 4; q2++) {
            float v0 = h_s[(g * 8 + 2 * q2) * 133 + n];
            float v1 = h_s[(g * 8 + 2 * q2 + 1) * 133 + n];
            hp[q2] = pk2f(v0, v1);
        }
        size_t off = (size_t)n * Nn + m0 + g * 8;
        *(uint4*)((char*)g_hT + off * 2) = make_uint4(hp[0], hp[1], hp[2], hp[3]);
    }

    // qmp partials: 8 warps x 8 rows
    float contrib = 0.0f;
    for (int rr = w * 8; rr < w * 8 + 8; rr++) {
        float hv0 = h_s[rr * 133 + l];
        float hv1 = h_s[rr * 133 + l + 32];
        float hv2 = h_s[rr * 133 + l + 64];
        float hv3 = h_s[rr * 133 + l + 96];
        float mu = 0.0f, lv = 0.0f;
        #pragma unroll
        for (int hh = 0; hh < 16; hh++) {
            const float* vr = &v1s[hh * 128];
            float s = hv0 * vr[l] + hv1 * vr[l + 32] + hv2 * vr[l + 64] + hv3 * vr[l + 96];
            #pragma unroll
            for (int o = 16; o > 0; o >>= 1) s += __shfl_xor_sync(0xffffffffu, s, o);
            float u = s + sml[hh];
            u = u > 0.0f ? u : 0.0f;
            mu += u * sml[16 + hh];
            lv += u * sml[32 + hh];
        }
        if (l == 0) {
            mu += sml[48]; lv += sml[49];
            float sig = (lv > 20.0f) ? lv : log1pf(expf(lv));
            contrib += 0.5f * mu * mu - logf(sig);
        }
    }
    __syncthreads();
    if (l == 0) sml[56 + w] = contrib;
    __syncthreads();
    if (t == 0) {
        float s = 0.0f;
        #pragma unroll
        for (int i = 0; i < 8; i++) s += sml[56 + i];
        g_qpart[blockIdx.x] = s;
    }
}

// ---------------- kernel 2: masked aggregation, fp16 HMMA, K-split --------
// Grid 128 = (mt 0..63) x (ksp 0..1): CTA = 128 rows x K-half 4096, N=128.
// Buffer: A fp16 [128][72] (18432B) | B fp16 [128][72] (18432B); x2 stages.
#define ASTR2  144
#define OFF_B2 18432
#define BUFSZ2 36864
#define NCH    64
#define K2_SMEM (2*BUFSZ2)

__global__ void __launch_bounds__(512, 1) k2_aggr(const int* __restrict__ adj)
{
    extern __shared__ __align__(128) char sm2[];
    const uint32_t sb = smem_u32(sm2);
    const int t = threadIdx.x;
    const int w = t >> 5, l = t & 31;
    const int wm = w & 3, wn = w >> 2;     // 4x4 warps; warp tile 32 rows x 32 cols
    const int mt = blockIdx.x >> 1, ksp = blockIdx.x & 1;
    const int m0 = mt * 128;
    const int kbase = ksp * 4096;

    // ---- loader indexing: 4 threads per row ----
    const int lr = t >> 2, lq = t & 3;
    const int* aSrc = adj + (size_t)(m0 + lr) * Nn + kbase + lq * 16;
    const uint32_t aDst = sb + lr * ASTR2 + lq * 32;
    const __half* bSrc = g_hT + (size_t)lr * Nn + kbase + lq * 16;
    const uint32_t bDst = sb + OFF_B2 + lr * ASTR2 + lq * 32;

    int4 rA[4];
    int dacc = 0;

#define LDA(c) do { \
    rA[0] = *(const int4*)(aSrc + (size_t)(c) * 64); \
    rA[1] = *(const int4*)(aSrc + (size_t)(c) * 64 + 4); \
    rA[2] = *(const int4*)(aSrc + (size_t)(c) * 64 + 8); \
    rA[3] = *(const int4*)(aSrc + (size_t)(c) * 64 + 12); } while (0)
#define STA(buf) do { \
    dacc += rA[0].x + rA[0].y + rA[0].z + rA[0].w + rA[1].x + rA[1].y + rA[1].z + rA[1].w \
          + rA[2].x + rA[2].y + rA[2].z + rA[2].w + rA[3].x + rA[3].y + rA[3].z + rA[3].w; \
    uint4 p0, p1; \
    p0.x = pkh(rA[0].x, rA[0].y); p0.y = pkh(rA[0].z, rA[0].w); \
    p0.z = pkh(rA[1].x, rA[1].y); p0.w = pkh(rA[1].z, rA[1].w); \
    p1.x = pkh(rA[2].x, rA[2].y); p1.y = pkh(rA[2].z, rA[2].w); \
    p1.z = pkh(rA[3].x, rA[3].y); p1.w = pkh(rA[3].z, rA[3].w); \
    STS128(aDst + (buf) * BUFSZ2, p0); \
    STS128(aDst + (buf) * BUFSZ2 + 16, p1); } while (0)
#define CPB(c, buf) do { \
    const char* _s = (const char*)(bSrc + (size_t)(c) * 64); \
    uint32_t _d = bDst + (buf) * BUFSZ2; \
    CP16(_d, _s); CP16(_d + 16, _s + 16); } while (0)

    float acc[2][4][4];
    #pragma unroll
    for (int m = 0; m < 2; m++)
        #pragma unroll
        for (int j = 0; j < 4; j++)
            #pragma unroll
            for (int q = 0; q < 4; q++) acc[m][j][q] = 0.0f;

    // prologue
    LDA(0);
    CPB(0, 0); CP_COMMIT();
    CPB(1, 1); CP_COMMIT();
    STA(0);
    LDA(1);

    // fragment addressing
    const uint32_t aLane = sb + (wm * 32 + (l & 15)) * ASTR2 + ((l >> 4) * 8) * 2;
    const int bn_lane = (l & 7) | ((l >> 4) << 3);
    const int bc_lane = ((l >> 3) & 1) << 3;
    const uint32_t bLane0 = sb + OFF_B2 + (wn * 32 + bn_lane) * ASTR2 + bc_lane * 2;
    const uint32_t bLane1 = bLane0 + 16 * ASTR2;

    for (int c = 0; c < NCH; c++) {
        CP_WAIT1();
        __syncthreads();
        const int buf = c & 1;
        if (c + 1 < NCH) STA(buf ^ 1);
        if (c + 2 < NCH) LDA(c + 2);

        const uint32_t aB0 = aLane + buf * BUFSZ2;
        const uint32_t aB1 = aB0 + 16 * ASTR2;
        const uint32_t bB0 = bLane0 + buf * BUFSZ2;
        const uint32_t bB1 = bLane1 + buf * BUFSZ2;
        #pragma unroll
        for (int kk = 0; kk < 64; kk += 16) {
            uint32_t a0[4], a1[4], b0, b1, b2, b3;
            LDSM4(a0[0], a0[1], a0[2], a0[3], aB0 + kk * 2);
            LDSM4(a1[0], a1[1], a1[2], a1[3], aB1 + kk * 2);
            LDSM4(b0, b1, b2, b3, bB0 + kk * 2);
            MMAH(acc[0][0], a0[0], a0[1], a0[2], a0[3], b0, b1);
            MMAH(acc[0][1], a0[0], a0[1], a0[2], a0[3], b2, b3);
            MMAH(acc[1][0], a1[0], a1[1], a1[2], a1[3], b0, b1);
            MMAH(acc[1][1], a1[0], a1[1], a1[2], a1[3], b2, b3);
            LDSM4(b0, b1, b2, b3, bB1 + kk * 2);
            MMAH(acc[0][2], a0[0], a0[1], a0[2], a0[3], b0, b1);
            MMAH(acc[0][3], a0[0], a0[1], a0[2], a0[3], b2, b3);
            MMAH(acc[1][2], a1[0], a1[1], a1[2], a1[3], b0, b1);
            MMAH(acc[1][3], a1[0], a1[1], a1[2], a1[3], b2, b3);
        }
        __syncthreads();
        if (c + 2 < NCH) CPB(c + 2, buf);
        CP_COMMIT();
    }
#undef LDA
#undef STA
#undef CPB

    // ---- degrees: reduce over the 4 loader threads per row ----
    dacc += __shfl_xor_sync(0xffffffffu, dacc, 1);
    dacc += __shfl_xor_sync(0xffffffffu, dacc, 2);
    if ((l & 3) == 0) g_degp[ksp * Nn + m0 + (t >> 2)] = (float)dacc;

    // ---- epilogue: K-split partials ----
    float* slab = g_part + (size_t)ksp * NF;
    #pragma unroll
    for (int m = 0; m < 2; m++) {
        const int row = m0 + wm * 32 + m * 16 + (l >> 2);
        #pragma unroll
        for (int j = 0; j < 4; j++) {
            const int col = wn * 32 + j * 8 + 2 * (l & 3);
            *(float2*)&slab[(size_t)row * FOUT + col] =
                make_float2(acc[m][j][0], acc[m][j][1]);
            *(float2*)&slab[(size_t)(row + 8) * FOUT + col] =
                make_float2(acc[m][j][2], acc[m][j][3]);
        }
    }
}

// ---------------- kernel 3: combine K-halves, scale, elu, qmp --------------
__global__ void __launch_bounds__(256) k3_final(float* __restrict__ out, int out_size)
{
    const int idx = blockIdx.x * 256 + threadIdx.x;
    if (idx < NF) {
        const int row = idx >> 7;
        float p = g_part[idx] + g_part[NF + idx];
        float d = g_degp[row] + g_degp[Nn + row];
        float v = d > 0.0f ? p / d : 0.0f;
        out[idx] = v > 0.0f ? v : expm1f(v);
    }
    if (blockIdx.x == 0 && threadIdx.x < 32) {
        float q = g_qpart[threadIdx.x] + g_qpart[threadIdx.x + 32] +
                  g_qpart[threadIdx.x + 64] + g_qpart[threadIdx.x + 96];
        #pragma unroll
        for (int o = 16; o > 0; o >>= 1) q += __shfl_xor_sync(0xffffffffu, q, o);
        if (threadIdx.x == 0 && out_size > NF) out[NF] = q;
    }
}

// ---------------- launch ----------------
extern "C" void kernel_launch(void* const* d_in, const int* in_sizes, int n_in,
                              void* d_out, int out_size) {
    const float* x   = (const float*)d_in[0];
    const int*   adj = (const int*)  d_in[1];
    const float* W   = (const float*)d_in[2];
    const float* w1  = (const float*)d_in[3];
    const float* b1  = (const float*)d_in[4];
    const float* w21 = (const float*)d_in[5];
    const float* b21 = (const float*)d_in[6];
    const float* w22 = (const float*)d_in[7];
    const float* b22 = (const float*)d_in[8];
    float* out = (float*)d_out;

    cudaFuncSetAttribute(k1_gemm, cudaFuncAttributeMaxDynamicSharedMemorySize, K1_SMEM);
    cudaFuncSetAttribute(k2_aggr, cudaFuncAttributeMaxDynamicSharedMemorySize, K2_SMEM);

    k0_convx<<<Nn * FIN / 1024, 256>>>(x);
    k0_convw<<<FOUT * FIN / 256, 256>>>(W);
    k1_gemm<<<Nn / 64, 256, K1_SMEM>>>(w1, b1, w21, b21, w22, b22);
    k2_aggr<<<128, 512, K2_SMEM>>>(adj);
    k3_final<<<(NF + 255) / 256, 256>>>(out, out_size);
}